// round 16
// baseline (speedup 1.0000x reference)
#include <cuda_runtime.h>
#include <cuda_bf16.h>
#include <math.h>

#define Bb   4
#define Hh   8
#define Tt   8192
#define Dd   64
#define Cc   64
#define Ww   128
#define BH   (Bb*Hh)
#define NROW (BH*Cc)
#define NOUT (BH*Tt*Dd)

__device__ float  g_dists[(size_t)NROW * Tt];
__device__ int    g_idx[NROW * Ww];
__device__ float  g_cnt[BH * Tt];
__device__ double g_loss;

// ---- bf16 helpers ------------------------------------------------
__device__ __forceinline__ unsigned pk2(float lo, float hi) {   // lower half = lo (first elem)
    unsigned r;
    asm("cvt.rn.bf16x2.f32 %0, %1, %2;" : "=r"(r) : "f"(hi), "f"(lo));
    return r;
}
__device__ __forceinline__ void bsplit(float x, float &h, float &l) {
    __nv_bfloat16 b = __float2bfloat16(x);
    h = __bfloat162float(b);
    l = x - h;
}
__device__ __forceinline__ void mma16(float* c, const unsigned* a, const unsigned* b) {
    asm("mma.sync.aligned.m16n8k16.row.col.f32.bf16.bf16.f32 "
        "{%0,%1,%2,%3}, {%4,%5,%6,%7}, {%8,%9}, {%0,%1,%2,%3};"
        : "+f"(c[0]), "+f"(c[1]), "+f"(c[2]), "+f"(c[3])
        : "r"(a[0]), "r"(a[1]), "r"(a[2]), "r"(a[3]), "r"(b[0]), "r"(b[1]));
}
__device__ __forceinline__ void ldsm4(unsigned* r, unsigned a) {
    asm volatile("ldmatrix.sync.aligned.m8n8.x4.shared.b16 {%0,%1,%2,%3}, [%4];"
        : "=r"(r[0]), "=r"(r[1]), "=r"(r[2]), "=r"(r[3]) : "r"(a));
}
__device__ __forceinline__ void ldsm4t(unsigned* r, unsigned a) {
    asm volatile("ldmatrix.sync.aligned.m8n8.x4.trans.shared.b16 {%0,%1,%2,%3}, [%4];"
        : "=r"(r[0]), "=r"(r[1]), "=r"(r[2]), "=r"(r[3]) : "r"(a));
}

// ------------------------------------------------------------------
// Phase 1: dists = l2norm(qk) @ means^T (bit-identical, do not touch)
// ------------------------------------------------------------------
__global__ void __launch_bounds__(128) k_dists(const float* __restrict__ qk,
                                               const float* __restrict__ means)
{
    __shared__ float sM[Cc * Dd];
    __shared__ float sMsq[Cc];
    __shared__ float sRed[128];

    const int bh  = blockIdx.y;
    const int h   = bh & (Hh - 1);
    const int tid = threadIdx.x;
    const int tok = blockIdx.x * 128 + tid;

    {
        const float4* src = (const float4*)(means + (size_t)h * Cc * Dd);
        float4* dst = (float4*)sM;
        for (int g = tid; g < Cc * Dd / 4; g += 128) dst[g] = src[g];
    }
    __syncthreads();
    if (tid < Cc) {
        float s = 0.f;
        const float* r = sM + tid * Dd;
        #pragma unroll
        for (int d = 0; d < Dd; d++) s = fmaf(r[d], r[d], s);
        sMsq[tid] = s;
    }
    __syncthreads();

    float4 r[16];
    const float4* qrow = (const float4*)(qk + ((size_t)bh * Tt + tok) * Dd);
    #pragma unroll
    for (int i = 0; i < 16; i++) r[i] = qrow[i];
    float nsq = 0.f;
    #pragma unroll
    for (int i = 0; i < 16; i++)
        nsq += r[i].x * r[i].x + r[i].y * r[i].y + r[i].z * r[i].z + r[i].w * r[i].w;
    const float inv = 1.0f / fmaxf(sqrtf(nsq), 1e-12f);
    #pragma unroll
    for (int i = 0; i < 16; i++) {
        r[i].x *= inv; r[i].y *= inv; r[i].z *= inv; r[i].w *= inv;
    }

    float best = -3.402823e38f;
    int   bc   = 0;
    float* drow = g_dists + (size_t)bh * Cc * Tt + tok;

    #pragma unroll 2
    for (int c = 0; c < Cc; c++) {
        const float4* m4 = (const float4*)(sM + c * Dd);
        float a0 = 0.f, a1 = 0.f, a2 = 0.f, a3 = 0.f;
        #pragma unroll
        for (int i = 0; i < 16; i++) {
            float4 m = m4[i];
            a0 = fmaf(r[i].x, m.x, a0);
            a1 = fmaf(r[i].y, m.y, a1);
            a2 = fmaf(r[i].z, m.z, a2);
            a3 = fmaf(r[i].w, m.w, a3);
        }
        float dist = (a0 + a1) + (a2 + a3);
        drow[(size_t)c * Tt] = dist;
        if (dist > best) { best = dist; bc = c; }
    }

    sRed[tid] = nsq * inv * inv - 2.0f * best + sMsq[bc];
    __syncthreads();
    for (int s = 64; s > 0; s >>= 1) {
        if (tid < s) sRed[tid] += sRed[tid + s];
        __syncthreads();
    }
    if (tid == 0) atomicAdd(&g_loss, (double)sRed[0]);
}

// ------------------------------------------------------------------
// Phase 2: exact top-128 per row; 512 threads (unchanged)
// ------------------------------------------------------------------
__global__ void __launch_bounds__(512) k_topk()
{
    __shared__ unsigned sk[Tt];
    __shared__ unsigned hist[256];
    __shared__ unsigned warpagg[16];
    __shared__ unsigned warpbase[16];
    __shared__ unsigned s_pivot;
    __shared__ int      s_need;

    const int row = blockIdx.x;
    const int tid = threadIdx.x;
    const int lane = tid & 31;
    const int wrp  = tid >> 5;
    const float* src = g_dists + (size_t)row * Tt;

    for (int i = tid; i < Tt; i += 512) {
        unsigned u = __float_as_uint(src[i]);
        u ^= (u & 0x80000000u) ? 0xFFFFFFFFu : 0x80000000u;
        sk[i] = u;
    }

    unsigned prefix = 0;
    int remaining = Ww;
    for (int pass = 0; pass < 4; pass++) {
        const int shift = 24 - pass * 8;
        const unsigned himask = (pass == 0) ? 0u : (0xFFFFFFFFu << (shift + 8));
        if (tid < 256) hist[tid] = 0;
        __syncthreads();
        for (int i = tid; i < Tt; i += 512) {
            unsigned u = sk[i];
            bool act = ((u & himask) == prefix);
            unsigned am = __ballot_sync(0xFFFFFFFFu, act);
            if (act) {
                int bin = (u >> shift) & 255;
                unsigned m = __match_any_sync(am, bin);
                if (lane == __ffs(m) - 1)
                    atomicAdd(&hist[bin], (unsigned)__popc(m));
            }
        }
        __syncthreads();
        #pragma unroll
        for (int off = 1; off < 256; off <<= 1) {
            unsigned vc = 0;
            if (tid < 256) vc = hist[tid] + ((tid + off < 256) ? hist[tid + off] : 0u);
            __syncthreads();
            if (tid < 256) hist[tid] = vc;
            __syncthreads();
        }
        if (tid < 256) {
            unsigned sb = hist[tid];
            unsigned sn = (tid == 255) ? 0u : hist[tid + 1];
            if (sb >= (unsigned)remaining && sn < (unsigned)remaining) {
                s_pivot = prefix | ((unsigned)tid << shift);
                s_need  = remaining - (int)sn;
            }
        }
        __syncthreads();
        prefix    = s_pivot;
        remaining = s_need;
        __syncthreads();
    }
    const unsigned pivot = prefix;
    const int need_eq = remaining;

    int gt = 0, eq = 0;
    const int base = tid * 16;
    for (int j = 0; j < 16; j++) {
        unsigned u = sk[base + j];
        gt += (u > pivot);
        eq += (u == pivot);
    }
    unsigned pk = ((unsigned)gt << 16) | (unsigned)eq;
    unsigned x = pk;
    #pragma unroll
    for (int o = 1; o < 32; o <<= 1) {
        unsigned y = __shfl_up_sync(0xFFFFFFFFu, x, o);
        if (lane >= o) x += y;
    }
    if (lane == 31) warpagg[wrp] = x;
    __syncthreads();
    if (tid == 0) {
        unsigned a = 0;
        for (int i = 0; i < 16; i++) { unsigned t0 = warpagg[i]; warpbase[i] = a; a += t0; }
    }
    __syncthreads();
    unsigned excl = x - pk + warpbase[wrp];
    int gb = (int)(excl >> 16);
    int eb = (int)(excl & 0xFFFFu);

    int* outp = g_idx + row * Ww;
    for (int j = 0; j < 16; j++) {
        int e = base + j;
        unsigned u = sk[e];
        if (u > pivot) {
            outp[gb + min(eb, need_eq)] = e;
            gb++;
        } else if (u == pivot) {
            if (eb < need_eq) outp[gb + eb] = e;
            eb++;
        }
    }
}

// ------------------------------------------------------------------
// Phase 2.5: counts from indices + loss write (unchanged)
// ------------------------------------------------------------------
__global__ void __launch_bounds__(512) k_cnt(float* __restrict__ out, int out_size)
{
    int i = blockIdx.x * 512 + threadIdx.x;
    int bh = i >> 13;
    atomicAdd(&g_cnt[bh * Tt + g_idx[i]], 1.0f);
    if (i == 0 && out_size > NOUT)
        out[NOUT] = (float)(g_loss * (1.0e-4 / (double)NOUT));
}

// ------------------------------------------------------------------
// Phase 3: bf16 split attention, 1024 threads; R16 = conflict-free
// smem traffic: V row-major + ldmatrix.trans B-frags; full-word
// bf16x2 softmax stores; ldmatrix A-frags in O loop.
// SMEM word map:
//   QH 0      [128][36]  (AH overlay [128][68] after S/R)
//   QL 4608   (AL overlay from word 8704)
//   WH 9216
//   WL 13824
//   VH 18432  [128][36] row-major V-hi bf16x2
//   VL 23040  [128][36]
//   D  27648  [128][132] fp32 scores
//   tail: INV 44544, ROW 44672, CNT 44800, IDX 44928 (total 45056)
// ------------------------------------------------------------------
#define QH 0
#define QL 4608
#define WH 9216
#define WL 13824
#define VH 18432
#define VL 23040
#define DOFF 27648
#define AH 0
#define AL 8704

__global__ void __launch_bounds__(1024, 1) k_attn(const float* __restrict__ qk,
                                                  const float* __restrict__ v,
                                                  const float* __restrict__ relw,
                                                  float* __restrict__ out)
{
    extern __shared__ float sm[];
    unsigned* usm = (unsigned*)sm;
    float* sD   = sm + DOFF;
    float* sInv = sm + 44544;
    float* sRow = sm + 44672;
    float* sCnt = sm + 44800;
    int*   sIdx = (int*)(sm + 44928);

    unsigned sb;
    asm("{ .reg .u64 t; cvta.to.shared.u64 t, %1; cvt.u32.u64 %0, t; }" : "=r"(sb) : "l"(sm));

    const int blk = blockIdx.x;
    const int bh  = blk >> 6;
    const int h   = bh & (Hh - 1);
    const int tid = threadIdx.x;
    const int l   = tid & 31;
    const int w   = tid >> 5;
    const int g   = l >> 2;
    const int t   = l & 3;

    if (tid < 128) {
        int ix = g_idx[blk * Ww + tid];
        sIdx[tid] = ix;
        sInv[tid] = 0.f;
        sCnt[tid] = 1.0f / (g_cnt[bh * Tt + ix] + 1e-5f);
    }
    __syncthreads();

    const float* qkb = qk + (size_t)bh * Tt * Dd;
    const float* vb  = v  + (size_t)bh * Tt * Dd;
    // gather + split/pack; Q, W, V all row-major bf16x2 (stride 36 words)
    {
        float4 qv[2], vv[2], rw[2];
        int ro[2], co[2];
        #pragma unroll
        for (int it = 0; it < 2; it++) {
            int gg = tid + it * 1024;
            int r = gg >> 4, c4 = (gg & 15) << 2;
            ro[it] = r; co[it] = c4;
            int off = sIdx[r] * Dd + c4;
            qv[it] = *(const float4*)(qkb + off);
            vv[it] = *(const float4*)(vb + off);
            rw[it] = *(const float4*)(relw + (r * Hh + h) * Dd + c4);
        }
        #pragma unroll
        for (int it = 0; it < 2; it++) {
            int r = ro[it], c4 = co[it];
            int qw = r * 36 + (c4 >> 1);
            float4 q = qv[it];
            atomicAdd(&sInv[r], q.x * q.x + q.y * q.y + q.z * q.z + q.w * q.w);
            float h0, l0, h1, l1, h2, l2, h3, l3;
            bsplit(q.x, h0, l0); bsplit(q.y, h1, l1);
            bsplit(q.z, h2, l2); bsplit(q.w, h3, l3);
            usm[QH + qw]     = pk2(h0, h1);
            usm[QH + qw + 1] = pk2(h2, h3);
            usm[QL + qw]     = pk2(l0, l1);
            usm[QL + qw + 1] = pk2(l2, l3);
            float4 rr = rw[it];
            bsplit(rr.x * 0.125f, h0, l0); bsplit(rr.y * 0.125f, h1, l1);
            bsplit(rr.z * 0.125f, h2, l2); bsplit(rr.w * 0.125f, h3, l3);
            usm[WH + qw]     = pk2(h0, h1);
            usm[WH + qw + 1] = pk2(h2, h3);
            usm[WL + qw]     = pk2(l0, l1);
            usm[WL + qw + 1] = pk2(l2, l3);
            float4 vf = vv[it];
            bsplit(vf.x, h0, l0); bsplit(vf.y, h1, l1);
            bsplit(vf.z, h2, l2); bsplit(vf.w, h3, l3);
            usm[VH + qw]     = pk2(h0, h1);
            usm[VH + qw + 1] = pk2(h2, h3);
            usm[VL + qw]     = pk2(l0, l1);
            usm[VL + qw + 1] = pk2(l2, l3);
        }
    }
    __syncthreads();
    if (tid < 128) sInv[tid] = 0.125f / fmaxf(sqrtf(sInv[tid]), 1e-12f);
    __syncthreads();

    // ---- merged S (3-pass) + R (2-pass): 8x4 grid of 16x32 tiles ----
    {
        const int wm = w >> 2, wn = w & 3;
        const bool doR = (16 * wm + 32 * wn >= 81);

        float accS[4][4];
        float accR[4][4];
        #pragma unroll
        for (int nt = 0; nt < 4; nt++)
            #pragma unroll
            for (int q = 0; q < 4; q++) { accS[nt][q] = 0.f; accR[nt][q] = 0.f; }

        #pragma unroll 1
        for (int kt = 0; kt < 4; kt++) {
            const int k0 = kt * 8;
            unsigned ah[4], al[4];
            const int ro = (16 * wm + g) * 36 + k0 + t;
            ah[0] = usm[QH + ro];              al[0] = usm[QL + ro];
            ah[1] = usm[QH + ro + 8 * 36];     al[1] = usm[QL + ro + 8 * 36];
            ah[2] = usm[QH + ro + 4];          al[2] = usm[QL + ro + 4];
            ah[3] = usm[QH + ro + 8 * 36 + 4]; al[3] = usm[QL + ro + 8 * 36 + 4];
            #pragma unroll
            for (int nt = 0; nt < 4; nt++) {
                const int rob = (32 * wn + 8 * nt + g) * 36 + k0 + t;
                unsigned bh2[2], bl2[2];
                bh2[0] = usm[QH + rob]; bh2[1] = usm[QH + rob + 4];
                bl2[0] = usm[QL + rob]; bl2[1] = usm[QL + rob + 4];
                mma16(accS[nt], ah, bh2);
                mma16(accS[nt], ah, bl2);
                mma16(accS[nt], al, bh2);
                if (doR) {
                    unsigned wh2[2], wl2[2];
                    wh2[0] = usm[WH + rob]; wh2[1] = usm[WH + rob + 4];
                    wl2[0] = usm[WL + rob]; wl2[1] = usm[WL + rob + 4];
                    mma16(accR[nt], ah, wh2);
                    mma16(accR[nt], ah, wl2);
                }
            }
        }
        // S epilogue
        #pragma unroll
        for (int nt = 0; nt < 4; nt++) {
            int row = 16 * wm + g;
            int col = 32 * wn + 8 * nt + 2 * t;
            float s0 = sInv[col], s1 = sInv[col + 1];
            sD[row * 132 + col]           = accS[nt][0] * s0;
            sD[row * 132 + col + 1]       = accS[nt][1] * s1;
            sD[(row + 8) * 132 + col]     = accS[nt][2] * s0;
            sD[(row + 8) * 132 + col + 1] = accS[nt][3] * s1;
        }
        __syncthreads();
        // R fold (_shift): dots[p][p+r-127] += R[p][r]
        if (doR) {
            #pragma unroll
            for (int nt = 0; nt < 4; nt++) {
                int p0r = 16 * wm + g;
                int col = 32 * wn + 8 * nt + 2 * t;
                int qc0 = p0r + col - 127;
                if (qc0 >= 0)     sD[p0r * 132 + qc0]           += accR[nt][0];
                if (qc0 + 1 >= 0) sD[p0r * 132 + qc0 + 1]       += accR[nt][1];
                int qc2 = p0r + 8 + col - 127;
                if (qc2 >= 0)     sD[(p0r + 8) * 132 + qc2]     += accR[nt][2];
                if (qc2 + 1 >= 0) sD[(p0r + 8) * 132 + qc2 + 1] += accR[nt][3];
            }
        }
    }
    __syncthreads();

    // ---- diag mask + softmax: warp w owns rows 4w..4w+3; lane l owns
    //      cols {2l, 2l+1, 64+2l, 64+2l+1}; full-word bf16x2 stores ----
    const int p0 = 4 * w;
    if (l < 4) sD[(p0 + l) * 132 + (p0 + l)] = -50000.0f;
    __syncwarp();
    {
        float vv[4][4], mx[4], sum[4];
        #pragma unroll
        for (int i = 0; i < 4; i++) {
            float2 da = *(const float2*)(sD + (p0 + i) * 132 + 2 * l);
            float2 db = *(const float2*)(sD + (p0 + i) * 132 + 64 + 2 * l);
            vv[i][0] = da.x; vv[i][1] = da.y; vv[i][2] = db.x; vv[i][3] = db.y;
            mx[i] = fmaxf(fmaxf(vv[i][0], vv[i][1]), fmaxf(vv[i][2], vv[i][3]));
        }
        #pragma unroll
        for (int o = 16; o > 0; o >>= 1)
            #pragma unroll
            for (int i = 0; i < 4; i++)
                mx[i] = fmaxf(mx[i], __shfl_xor_sync(0xffffffffu, mx[i], o));
        #pragma unroll
        for (int i = 0; i < 4; i++) {
            int p = p0 + i;
            float e0 = __expf(vv[i][0] - mx[i]);
            float e1 = __expf(vv[i][1] - mx[i]);
            float e2 = __expf(vv[i][2] - mx[i]);
            float e3 = __expf(vv[i][3] - mx[i]);
            sum[i] = (e0 + e1) + (e2 + e3);
            float h0, l0, h1, l1, h2, l2, h3, l3;
            bsplit(e0, h0, l0); bsplit(e1, h1, l1);
            bsplit(e2, h2, l2); bsplit(e3, h3, l3);
            usm[AH + p * 68 + l]      = pk2(h0, h1);
            usm[AH + p * 68 + 32 + l] = pk2(h2, h3);
            usm[AL + p * 68 + l]      = pk2(l0, l1);
            usm[AL + p * 68 + 32 + l] = pk2(l2, l3);
        }
        #pragma unroll
        for (int o = 16; o > 0; o >>= 1)
            #pragma unroll
            for (int i = 0; i < 4; i++)
                sum[i] += __shfl_xor_sync(0xffffffffu, sum[i], o);
        if (l == 0) {
            #pragma unroll
            for (int i = 0; i < 4; i++) sRow[p0 + i] = sCnt[p0 + i] / sum[i];
        }
    }
    __syncthreads();

    // ---- O = attn.V (3-pass): 8x4 grid of 16x16 tiles, ldmatrix ----
    {
        const int om = w >> 2, on = w & 3;
        const int i4 = l >> 3, j8 = l & 7;
        float acc[2][4];
        #pragma unroll
        for (int nt = 0; nt < 2; nt++)
            #pragma unroll
            for (int q = 0; q < 4; q++) acc[nt][q] = 0.f;

        #pragma unroll 2
        for (int kt = 0; kt < 8; kt++) {
            // A: attn rows, non-trans; M0=r0-7/k0-7, M1=r8-15/k0-7, M2=r0-7/k8-15, M3=r8-15/k8-15
            unsigned arow = AH + (16 * om + 8 * (i4 & 1) + j8) * 68 + 8 * kt + 4 * (i4 >> 1);
            unsigned ah4[4], al4[4];
            ldsm4(ah4, sb + 4 * arow);
            ldsm4(al4, sb + 4 * (arow + (AL - AH)));
            // B: V rows (tokens), trans; M0=tok0-7/d0-7(b0,nt0), M1=tok8-15/d0-7(b1,nt0), M2,M3=d8-15(nt1)
            unsigned brow = VH + (16 * kt + 8 * (i4 & 1) + j8) * 36 + 8 * on + 4 * (i4 >> 1);
            unsigned bvh[4], bvl[4];
            ldsm4t(bvh, sb + 4 * brow);
            ldsm4t(bvl, sb + 4 * (brow + (VL - VH)));
            #pragma unroll
            for (int nt = 0; nt < 2; nt++) {
                mma16(acc[nt], ah4, bvh + 2 * nt);
                mma16(acc[nt], ah4, bvl + 2 * nt);
                mma16(acc[nt], al4, bvh + 2 * nt);
            }
        }
        int row = 16 * om + g;
        float r0 = sRow[row], r1 = sRow[row + 8];
        float* d0 = out + ((size_t)bh * Tt + sIdx[row]) * Dd;
        float* d1 = out + ((size_t)bh * Tt + sIdx[row + 8]) * Dd;
        #pragma unroll
        for (int nt = 0; nt < 2; nt++) {
            int col = 16 * on + 8 * nt + 2 * t;
            atomicAdd(d0 + col,     acc[nt][0] * r0);
            atomicAdd(d0 + col + 1, acc[nt][1] * r0);
            atomicAdd(d1 + col,     acc[nt][2] * r1);
            atomicAdd(d1 + col + 1, acc[nt][3] * r1);
        }
    }
}

extern "C" void kernel_launch(void* const* d_in, const int* in_sizes, int n_in,
                              void* d_out, int out_size)
{
    const float* qk    = (const float*)d_in[0];
    const float* v     = (const float*)d_in[1];
    const float* means = (const float*)d_in[2];
    const float* relw  = (const float*)d_in[3];
    float* out = (float*)d_out;

    cudaMemsetAsync(d_out, 0, (size_t)out_size * sizeof(float));
    void* cp = 0; cudaGetSymbolAddress(&cp, g_cnt);
    cudaMemsetAsync(cp, 0, (size_t)BH * Tt * sizeof(float));
    void* lp = 0; cudaGetSymbolAddress(&lp, g_loss);
    cudaMemsetAsync(lp, 0, sizeof(double));

    dim3 g1(Tt / 128, BH);
    k_dists<<<g1, 128>>>(qk, means);

    k_topk<<<NROW, 512>>>();

    k_cnt<<<NROW * Ww / 512, 512>>>(out, out_size);

    const int smem_attn = 45056 * 4;    // 180,224 B
    cudaFuncSetAttribute(k_attn, cudaFuncAttributeMaxDynamicSharedMemorySize, smem_attn);
    k_attn<<<NROW, 1024, smem_attn>>>(qk, v, relw, out);
}

// round 17
// speedup vs baseline: 1.4533x; 1.4533x over previous
#include <cuda_runtime.h>
#include <cuda_bf16.h>
#include <math.h>

#define Bb   4
#define Hh   8
#define Tt   8192
#define Dd   64
#define Cc   64
#define Ww   128
#define BH   (Bb*Hh)
#define NROW (BH*Cc)
#define NOUT (BH*Tt*Dd)

__device__ float  g_dists[(size_t)NROW * Tt];
__device__ int    g_idx[NROW * Ww];
__device__ float  g_cnt[BH * Tt];
__device__ double g_loss;

// ---- bf16 helpers ------------------------------------------------
__device__ __forceinline__ unsigned pk2(float lo, float hi) {   // lower half = lo (first k elem)
    unsigned r;
    asm("cvt.rn.bf16x2.f32 %0, %1, %2;" : "=r"(r) : "f"(hi), "f"(lo));
    return r;
}
__device__ __forceinline__ void bsplit(float x, float &h, float &l) {
    __nv_bfloat16 b = __float2bfloat16(x);
    h = __bfloat162float(b);
    l = x - h;
}
// D += A(16x16) * B(16x8), bf16 inputs, f32 accum
__device__ __forceinline__ void mma16(float* c, const unsigned* a, const unsigned* b) {
    asm("mma.sync.aligned.m16n8k16.row.col.f32.bf16.bf16.f32 "
        "{%0,%1,%2,%3}, {%4,%5,%6,%7}, {%8,%9}, {%0,%1,%2,%3};"
        : "+f"(c[0]), "+f"(c[1]), "+f"(c[2]), "+f"(c[3])
        : "r"(a[0]), "r"(a[1]), "r"(a[2]), "r"(a[3]), "r"(b[0]), "r"(b[1]));
}

// ------------------------------------------------------------------
// Phase 1: dists = l2norm(qk) @ means^T (bit-identical, do not touch)
// ------------------------------------------------------------------
__global__ void __launch_bounds__(128) k_dists(const float* __restrict__ qk,
                                               const float* __restrict__ means)
{
    __shared__ float sM[Cc * Dd];
    __shared__ float sMsq[Cc];
    __shared__ float sRed[128];

    const int bh  = blockIdx.y;
    const int h   = bh & (Hh - 1);
    const int tid = threadIdx.x;
    const int tok = blockIdx.x * 128 + tid;

    {
        const float4* src = (const float4*)(means + (size_t)h * Cc * Dd);
        float4* dst = (float4*)sM;
        for (int g = tid; g < Cc * Dd / 4; g += 128) dst[g] = src[g];
    }
    __syncthreads();
    if (tid < Cc) {
        float s = 0.f;
        const float* r = sM + tid * Dd;
        #pragma unroll
        for (int d = 0; d < Dd; d++) s = fmaf(r[d], r[d], s);
        sMsq[tid] = s;
    }
    __syncthreads();

    float4 r[16];
    const float4* qrow = (const float4*)(qk + ((size_t)bh * Tt + tok) * Dd);
    #pragma unroll
    for (int i = 0; i < 16; i++) r[i] = qrow[i];
    float nsq = 0.f;
    #pragma unroll
    for (int i = 0; i < 16; i++)
        nsq += r[i].x * r[i].x + r[i].y * r[i].y + r[i].z * r[i].z + r[i].w * r[i].w;
    const float inv = 1.0f / fmaxf(sqrtf(nsq), 1e-12f);
    #pragma unroll
    for (int i = 0; i < 16; i++) {
        r[i].x *= inv; r[i].y *= inv; r[i].z *= inv; r[i].w *= inv;
    }

    float best = -3.402823e38f;
    int   bc   = 0;
    float* drow = g_dists + (size_t)bh * Cc * Tt + tok;

    #pragma unroll 2
    for (int c = 0; c < Cc; c++) {
        const float4* m4 = (const float4*)(sM + c * Dd);
        float a0 = 0.f, a1 = 0.f, a2 = 0.f, a3 = 0.f;
        #pragma unroll
        for (int i = 0; i < 16; i++) {
            float4 m = m4[i];
            a0 = fmaf(r[i].x, m.x, a0);
            a1 = fmaf(r[i].y, m.y, a1);
            a2 = fmaf(r[i].z, m.z, a2);
            a3 = fmaf(r[i].w, m.w, a3);
        }
        float dist = (a0 + a1) + (a2 + a3);
        drow[(size_t)c * Tt] = dist;
        if (dist > best) { best = dist; bc = c; }
    }

    sRed[tid] = nsq * inv * inv - 2.0f * best + sMsq[bc];
    __syncthreads();
    for (int s = 64; s > 0; s >>= 1) {
        if (tid < s) sRed[tid] += sRed[tid + s];
        __syncthreads();
    }
    if (tid == 0) atomicAdd(&g_loss, (double)sRed[0]);
}

// ------------------------------------------------------------------
// Phase 2: exact top-128 per row; 512 threads (unchanged)
// ------------------------------------------------------------------
__global__ void __launch_bounds__(512) k_topk()
{
    __shared__ unsigned sk[Tt];
    __shared__ unsigned hist[256];
    __shared__ unsigned warpagg[16];
    __shared__ unsigned warpbase[16];
    __shared__ unsigned s_pivot;
    __shared__ int      s_need;

    const int row = blockIdx.x;
    const int tid = threadIdx.x;
    const int lane = tid & 31;
    const int wrp  = tid >> 5;
    const float* src = g_dists + (size_t)row * Tt;

    for (int i = tid; i < Tt; i += 512) {
        unsigned u = __float_as_uint(src[i]);
        u ^= (u & 0x80000000u) ? 0xFFFFFFFFu : 0x80000000u;
        sk[i] = u;
    }

    unsigned prefix = 0;
    int remaining = Ww;
    for (int pass = 0; pass < 4; pass++) {
        const int shift = 24 - pass * 8;
        const unsigned himask = (pass == 0) ? 0u : (0xFFFFFFFFu << (shift + 8));
        if (tid < 256) hist[tid] = 0;
        __syncthreads();
        for (int i = tid; i < Tt; i += 512) {
            unsigned u = sk[i];
            bool act = ((u & himask) == prefix);
            unsigned am = __ballot_sync(0xFFFFFFFFu, act);
            if (act) {
                int bin = (u >> shift) & 255;
                unsigned m = __match_any_sync(am, bin);
                if (lane == __ffs(m) - 1)
                    atomicAdd(&hist[bin], (unsigned)__popc(m));
            }
        }
        __syncthreads();
        #pragma unroll
        for (int off = 1; off < 256; off <<= 1) {
            unsigned vc = 0;
            if (tid < 256) vc = hist[tid] + ((tid + off < 256) ? hist[tid + off] : 0u);
            __syncthreads();
            if (tid < 256) hist[tid] = vc;
            __syncthreads();
        }
        if (tid < 256) {
            unsigned sb = hist[tid];
            unsigned sn = (tid == 255) ? 0u : hist[tid + 1];
            if (sb >= (unsigned)remaining && sn < (unsigned)remaining) {
                s_pivot = prefix | ((unsigned)tid << shift);
                s_need  = remaining - (int)sn;
            }
        }
        __syncthreads();
        prefix    = s_pivot;
        remaining = s_need;
        __syncthreads();
    }
    const unsigned pivot = prefix;
    const int need_eq = remaining;

    int gt = 0, eq = 0;
    const int base = tid * 16;
    for (int j = 0; j < 16; j++) {
        unsigned u = sk[base + j];
        gt += (u > pivot);
        eq += (u == pivot);
    }
    unsigned pk = ((unsigned)gt << 16) | (unsigned)eq;
    unsigned x = pk;
    #pragma unroll
    for (int o = 1; o < 32; o <<= 1) {
        unsigned y = __shfl_up_sync(0xFFFFFFFFu, x, o);
        if (lane >= o) x += y;
    }
    if (lane == 31) warpagg[wrp] = x;
    __syncthreads();
    if (tid == 0) {
        unsigned a = 0;
        for (int i = 0; i < 16; i++) { unsigned t0 = warpagg[i]; warpbase[i] = a; a += t0; }
    }
    __syncthreads();
    unsigned excl = x - pk + warpbase[wrp];
    int gb = (int)(excl >> 16);
    int eb = (int)(excl & 0xFFFFu);

    int* outp = g_idx + row * Ww;
    for (int j = 0; j < 16; j++) {
        int e = base + j;
        unsigned u = sk[e];
        if (u > pivot) {
            outp[gb + min(eb, need_eq)] = e;
            gb++;
        } else if (u == pivot) {
            if (eb < need_eq) outp[gb + eb] = e;
            eb++;
        }
    }
}

// ------------------------------------------------------------------
// Phase 2.5: counts from indices + loss write (unchanged)
// ------------------------------------------------------------------
__global__ void __launch_bounds__(512) k_cnt(float* __restrict__ out, int out_size)
{
    int i = blockIdx.x * 512 + threadIdx.x;
    int bh = i >> 13;
    atomicAdd(&g_cnt[bh * Tt + g_idx[i]], 1.0f);
    if (i == 0 && out_size > NOUT)
        out[NOUT] = (float)(g_loss * (1.0e-4 / (double)NOUT));
}

// ------------------------------------------------------------------
// Phase 3: bf16 split attention, 1024 threads (R15 base).
// R17: V^T token-pair index rotation swizzle: word = col*68 +
// ((s + col) & 63). Store bank 8-way -> 2-way; read 1 -> <=2-way.
// SMEM word map unchanged from R14/R15.
// ------------------------------------------------------------------
#define QH 0
#define QL 4608
#define WH 9216
#define WL 13824
#define VH 18432
#define VL 22784
#define DOFF 27136
#define AH 0
#define AL 8704

__global__ void __launch_bounds__(1024, 1) k_attn(const float* __restrict__ qk,
                                                  const float* __restrict__ v,
                                                  const float* __restrict__ relw,
                                                  float* __restrict__ out)
{
    extern __shared__ float sm[];
    unsigned* usm = (unsigned*)sm;
    float* sD   = sm + DOFF;          // [128][132]
    float* sInv = sm + 44032;
    float* sRow = sm + 44160;
    float* sCnt = sm + 44288;
    int*   sIdx = (int*)(sm + 44416);

    const int blk = blockIdx.x;
    const int bh  = blk >> 6;
    const int h   = bh & (Hh - 1);
    const int tid = threadIdx.x;
    const int l   = tid & 31;
    const int w   = tid >> 5;          // 0..31
    const int g   = l >> 2;
    const int t   = l & 3;

    if (tid < 128) {
        int ix = g_idx[blk * Ww + tid];
        sIdx[tid] = ix;
        sInv[tid] = 0.f;
        sCnt[tid] = 1.0f / (g_cnt[bh * Tt + ix] + 1e-5f);
    }
    __syncthreads();

    const float* qkb = qk + (size_t)bh * Tt * Dd;
    const float* vb  = v  + (size_t)bh * Tt * Dd;
    // gather + split/pack (bf16); V stored transposed (token pairs packed,
    // rotation-swizzled within each column)
    {
        float4 qv[2], vv[2], rw[2];
        int ro[2], co[2];
        #pragma unroll
        for (int it = 0; it < 2; it++) {
            int gg = tid + it * 1024;
            int r = gg >> 4, c4 = (gg & 15) << 2;
            ro[it] = r; co[it] = c4;
            int off = sIdx[r] * Dd + c4;
            qv[it] = *(const float4*)(qkb + off);
            vv[it] = *(const float4*)(vb + off);
            rw[it] = *(const float4*)(relw + (r * Hh + h) * Dd + c4);
        }
        #pragma unroll
        for (int it = 0; it < 2; it++) {
            int r = ro[it], c4 = co[it];
            float4 q = qv[it];
            atomicAdd(&sInv[r], q.x * q.x + q.y * q.y + q.z * q.z + q.w * q.w);
            float h0, l0, h1, l1, h2, l2, h3, l3;
            bsplit(q.x, h0, l0); bsplit(q.y, h1, l1);
            bsplit(q.z, h2, l2); bsplit(q.w, h3, l3);
            int qw = r * 36 + (c4 >> 1);
            usm[QH + qw]     = pk2(h0, h1);
            usm[QH + qw + 1] = pk2(h2, h3);
            usm[QL + qw]     = pk2(l0, l1);
            usm[QL + qw + 1] = pk2(l2, l3);
            float4 rr = rw[it];
            bsplit(rr.x * 0.125f, h0, l0); bsplit(rr.y * 0.125f, h1, l1);
            bsplit(rr.z * 0.125f, h2, l2); bsplit(rr.w * 0.125f, h3, l3);
            usm[WH + qw]     = pk2(h0, h1);
            usm[WH + qw + 1] = pk2(h2, h3);
            usm[WL + qw]     = pk2(l0, l1);
            usm[WL + qw + 1] = pk2(l2, l3);
            float4 vf = vv[it];
            float vh[4], vl[4];
            bsplit(vf.x, vh[0], vl[0]); bsplit(vf.y, vh[1], vl[1]);
            bsplit(vf.z, vh[2], vl[2]); bsplit(vf.w, vh[3], vl[3]);
            int s = r >> 1;
            #pragma unroll
            for (int i = 0; i < 4; i++) {
                int col = c4 + i;
                int sw = (s + col) & 63;     // rotation swizzle
                size_t byh = ((size_t)(VH + col * 68 + sw) << 2) + ((r & 1) << 1);
                *(__nv_bfloat16*)((char*)usm + byh) = __float2bfloat16(vh[i]);
                size_t byl = ((size_t)(VL + col * 68 + sw) << 2) + ((r & 1) << 1);
                *(__nv_bfloat16*)((char*)usm + byl) = __float2bfloat16(vl[i]);
            }
        }
    }
    __syncthreads();
    if (tid < 128) sInv[tid] = 0.125f / fmaxf(sqrtf(sInv[tid]), 1e-12f);
    __syncthreads();

    // ---- merged S (3-pass) + R (2-pass): 8x4 grid of 16x32 tiles ----
    {
        const int wm = w >> 2, wn = w & 3;
        const bool doR = (16 * wm + 32 * wn >= 81);

        float accS[4][4];
        float accR[4][4];
        #pragma unroll
        for (int nt = 0; nt < 4; nt++)
            #pragma unroll
            for (int q = 0; q < 4; q++) { accS[nt][q] = 0.f; accR[nt][q] = 0.f; }

        #pragma unroll 1
        for (int kt = 0; kt < 4; kt++) {
            const int k0 = kt * 8;
            unsigned ah[4], al[4];
            const int ro = (16 * wm + g) * 36 + k0 + t;
            ah[0] = usm[QH + ro];            al[0] = usm[QL + ro];
            ah[1] = usm[QH + ro + 8 * 36];   al[1] = usm[QL + ro + 8 * 36];
            ah[2] = usm[QH + ro + 4];        al[2] = usm[QL + ro + 4];
            ah[3] = usm[QH + ro + 8 * 36 + 4]; al[3] = usm[QL + ro + 8 * 36 + 4];
            #pragma unroll
            for (int nt = 0; nt < 4; nt++) {
                const int rob = (32 * wn + 8 * nt + g) * 36 + k0 + t;
                unsigned bh2[2], bl2[2];
                bh2[0] = usm[QH + rob]; bh2[1] = usm[QH + rob + 4];
                bl2[0] = usm[QL + rob]; bl2[1] = usm[QL + rob + 4];
                mma16(accS[nt], ah, bh2);
                mma16(accS[nt], ah, bl2);
                mma16(accS[nt], al, bh2);
                if (doR) {
                    unsigned wh2[2], wl2[2];
                    wh2[0] = usm[WH + rob]; wh2[1] = usm[WH + rob + 4];
                    wl2[0] = usm[WL + rob]; wl2[1] = usm[WL + rob + 4];
                    mma16(accR[nt], ah, wh2);
                    mma16(accR[nt], ah, wl2);
                }
            }
        }
        // S epilogue
        #pragma unroll
        for (int nt = 0; nt < 4; nt++) {
            int row = 16 * wm + g;
            int col = 32 * wn + 8 * nt + 2 * t;
            float s0 = sInv[col], s1 = sInv[col + 1];
            sD[row * 132 + col]           = accS[nt][0] * s0;
            sD[row * 132 + col + 1]       = accS[nt][1] * s1;
            sD[(row + 8) * 132 + col]     = accS[nt][2] * s0;
            sD[(row + 8) * 132 + col + 1] = accS[nt][3] * s1;
        }
        __syncthreads();
        // R fold (_shift): dots[p][p+r-127] += R[p][r]
        if (doR) {
            #pragma unroll
            for (int nt = 0; nt < 4; nt++) {
                int p0r = 16 * wm + g;
                int col = 32 * wn + 8 * nt + 2 * t;
                int qc0 = p0r + col - 127;
                if (qc0 >= 0)     sD[p0r * 132 + qc0]           += accR[nt][0];
                if (qc0 + 1 >= 0) sD[p0r * 132 + qc0 + 1]       += accR[nt][1];
                int qc2 = p0r + 8 + col - 127;
                if (qc2 >= 0)     sD[(p0r + 8) * 132 + qc2]     += accR[nt][2];
                if (qc2 + 1 >= 0) sD[(p0r + 8) * 132 + qc2 + 1] += accR[nt][3];
            }
        }
    }
    __syncthreads();

    // ---- diag mask + softmax: warp w owns rows 4w..4w+3 ----
    const int p0 = 4 * w;
    if (l < 4) sD[(p0 + l) * 132 + (p0 + l)] = -50000.0f;
    __syncwarp();
    {
        float vv[4][4], mx[4], sum[4];
        #pragma unroll
        for (int i = 0; i < 4; i++) {
            mx[i] = -3.402823e38f;
            #pragma unroll
            for (int j = 0; j < 4; j++) {
                vv[i][j] = sD[(p0 + i) * 132 + l + 32 * j];
                mx[i] = fmaxf(mx[i], vv[i][j]);
            }
        }
        #pragma unroll
        for (int o = 16; o > 0; o >>= 1)
            #pragma unroll
            for (int i = 0; i < 4; i++)
                mx[i] = fmaxf(mx[i], __shfl_xor_sync(0xffffffffu, mx[i], o));
        #pragma unroll
        for (int i = 0; i < 4; i++) {
            sum[i] = 0.f;
            int p = p0 + i;
            #pragma unroll
            for (int j = 0; j < 4; j++) {
                float e = __expf(vv[i][j] - mx[i]);
                sum[i] += e;
                float eh, el;
                bsplit(e, eh, el);
                int c = l + 32 * j;
                size_t by = ((size_t)(p * 68 + (c >> 1)) << 2) + ((c & 1) << 1);
                *(__nv_bfloat16*)((char*)usm + (((size_t)AH) << 2) + by) = __float2bfloat16(eh);
                *(__nv_bfloat16*)((char*)usm + (((size_t)AL) << 2) + by) = __float2bfloat16(el);
            }
        }
        #pragma unroll
        for (int o = 16; o > 0; o >>= 1)
            #pragma unroll
            for (int i = 0; i < 4; i++)
                sum[i] += __shfl_xor_sync(0xffffffffu, sum[i], o);
        if (l == 0) {
            #pragma unroll
            for (int i = 0; i < 4; i++) sRow[p0 + i] = sCnt[p0 + i] / sum[i];
        }
    }
    __syncthreads();

    // ---- O = attn.V (3-pass): 8x4 grid of 16x16 tiles ----
    {
        const int om = w >> 2, on = w & 3;
        float acc[2][4];
        #pragma unroll
        for (int nt = 0; nt < 2; nt++)
            #pragma unroll
            for (int q = 0; q < 4; q++) acc[nt][q] = 0.f;

        #pragma unroll 2
        for (int kt = 0; kt < 8; kt++) {
            const int k0 = kt * 8;
            unsigned ah4[4], al4[4];
            const int ro = (16 * om + g) * 68 + k0 + t;
            ah4[0] = usm[AH + ro];              al4[0] = usm[AL + ro];
            ah4[1] = usm[AH + ro + 8 * 68];     al4[1] = usm[AL + ro + 8 * 68];
            ah4[2] = usm[AH + ro + 4];          al4[2] = usm[AL + ro + 4];
            ah4[3] = usm[AH + ro + 8 * 68 + 4]; al4[3] = usm[AL + ro + 8 * 68 + 4];
            #pragma unroll
            for (int nt = 0; nt < 2; nt++) {
                const int colb = 16 * on + 8 * nt + g;
                const int base2 = colb * 68;
                int s0 = (k0 + t + colb) & 63;        // rotation swizzle
                int s1 = (k0 + t + 4 + colb) & 63;
                unsigned bh2[2], bl2[2];
                bh2[0] = usm[VH + base2 + s0]; bh2[1] = usm[VH + base2 + s1];
                bl2[0] = usm[VL + base2 + s0]; bl2[1] = usm[VL + base2 + s1];
                mma16(acc[nt], ah4, bh2);
                mma16(acc[nt], ah4, bl2);
                mma16(acc[nt], al4, bh2);
            }
        }
        int row = 16 * om + g;
        float r0 = sRow[row], r1 = sRow[row + 8];
        float* d0 = out + ((size_t)bh * Tt + sIdx[row]) * Dd;
        float* d1 = out + ((size_t)bh * Tt + sIdx[row + 8]) * Dd;
        #pragma unroll
        for (int nt = 0; nt < 2; nt++) {
            int col = 16 * on + 8 * nt + 2 * t;
            atomicAdd(d0 + col,     acc[nt][0] * r0);
            atomicAdd(d0 + col + 1, acc[nt][1] * r0);
            atomicAdd(d1 + col,     acc[nt][2] * r1);
            atomicAdd(d1 + col + 1, acc[nt][3] * r1);
        }
    }
}

extern "C" void kernel_launch(void* const* d_in, const int* in_sizes, int n_in,
                              void* d_out, int out_size)
{
    const float* qk    = (const float*)d_in[0];
    const float* v     = (const float*)d_in[1];
    const float* means = (const float*)d_in[2];
    const float* relw  = (const float*)d_in[3];
    float* out = (float*)d_out;

    cudaMemsetAsync(d_out, 0, (size_t)out_size * sizeof(float));
    void* cp = 0; cudaGetSymbolAddress(&cp, g_cnt);
    cudaMemsetAsync(cp, 0, (size_t)BH * Tt * sizeof(float));
    void* lp = 0; cudaGetSymbolAddress(&lp, g_loss);
    cudaMemsetAsync(lp, 0, sizeof(double));

    dim3 g1(Tt / 128, BH);
    k_dists<<<g1, 128>>>(qk, means);

    k_topk<<<NROW, 512>>>();

    k_cnt<<<NROW * Ww / 512, 512>>>(out, out_size);

    const int smem_attn = 44544 * 4;    // 178,176 B
    cudaFuncSetAttribute(k_attn, cudaFuncAttributeMaxDynamicSharedMemorySize, smem_attn);
    k_attn<<<NROW, 1024, smem_attn>>>(qk, v, relw, out);
}